// round 9
// baseline (speedup 1.0000x reference)
#include <cuda_runtime.h>

// DynamicMaskHead fused kernel, round 9:
//  - 2 pixels per thread, f32x2 lanes = the pixel pair: feats are consumed
//    DIRECTLY as loaded float2s (zero lane shuffling), weights are duplicated
//    in smem so LDS gives ready [w,w] splats (warp-uniform broadcast)
//  - c-outer layers: at most one accumulator pair live -> ~75 live regs
//  - __launch_bounds__(128,6): 6 blocks/SM, 24 warps (occupancy is the lever;
//    the 4px variant is register-walled at 128 with issue stuck at 56%)
//  - incremental index math, no integer division
//  - fused aligned_bilinear x2 from smem logit tile

#define WW    192
#define HH    128
#define HWSZ  (192*128)
#define CIN   8
#define TH    16
#define NROWS (TH + 1)           // +1 halo row above
#define PPR   (WW/2)             // 96 pixel-pair units per row
#define NUNIT (NROWS * PPR)      // 1632
#define OWW   384
#define OHH   256
#define NP    169

__device__ __forceinline__ float2 ffma2(float2 a, float2 b, float2 c) {
    float2 d;
    asm("fma.rn.f32x2 %0, %1, %2, %3;"
        : "=l"(reinterpret_cast<unsigned long long&>(d))
        : "l"(reinterpret_cast<unsigned long long&>(a)),
          "l"(reinterpret_cast<unsigned long long&>(b)),
          "l"(reinterpret_cast<unsigned long long&>(c)));
    return d;
}
__device__ __forceinline__ float2 relu2(float2 v) {
    return make_float2(fmaxf(v.x, 0.f), fmaxf(v.y, 0.f));
}
__device__ __forceinline__ float2 f2(float a, float b) { return make_float2(a, b); }

__global__ __launch_bounds__(128, 6) void dyn_mask_head_kernel(
    const float* __restrict__ mask_feats,   // [2, 8, 128, 192]
    const float* __restrict__ params,       // [n_inst, 169]
    const float* __restrict__ locs,         // [n_inst, 2] (x, y)
    const float* __restrict__ soi,          // [5]
    const int*   __restrict__ im_inds,      // [n_inst]
    const int*   __restrict__ fpn_levels,   // [n_inst]
    float*       __restrict__ out)          // [n_inst, 1, 256, 384]
{
    const int n   = blockIdx.y;
    const int r0  = blockIdx.x * TH;
    const int tid = threadIdx.x;

    __shared__ __align__(16) float sw0[8][24]; // w0..w9 dup(20) + bias dup(2) + pad
    __shared__ __align__(16) float sw1[8][20]; // w0..w7 dup(16) + bias dup(2) + pad
    __shared__ __align__(16) float sw2[20];    // w dup(16) + bias dup(2) + pad
    __shared__ __align__(16) float sL[NROWS][WW];

    {
        const float* p = params + n * NP;
        for (int t = tid; t < NP; t += 128) {
            float v = __ldg(p + t);
            if (t < 80) {
                int c = t / 10, j = t - 10 * c;
                sw0[c][2*j] = v; sw0[c][2*j+1] = v;
            } else if (t < 144) {
                int q = t - 80; int c = q >> 3, j = q & 7;
                sw1[c][2*j] = v; sw1[c][2*j+1] = v;
            } else if (t < 152) {
                int j = t - 144;
                sw2[2*j] = v; sw2[2*j+1] = v;
            } else if (t < 160) {
                int c = t - 152;
                sw0[c][20] = v; sw0[c][21] = v;
            } else if (t < 168) {
                int c = t - 160;
                sw1[c][16] = v; sw1[c][17] = v;
            } else {
                sw2[16] = v; sw2[17] = v;
            }
        }
    }
    __syncthreads();

    const int   im  = im_inds[n];
    const float inv = 1.0f / soi[fpn_levels[n]];
    const float lx  = locs[2*n + 0];
    const float ly  = locs[2*n + 1];
    const float* fb = mask_feats + (size_t)im * (CIN * HWSZ);
    const float s8  = 8.0f * inv;

    // ---- phase 1: logits, one pixel PAIR per thread per iteration ----
    // unit index i = rl*96 + m; per-iter stride 128 = 1 row + 32 pairs
    int rl = (tid >= 96) ? 1 : 0;
    int m  = tid - rl * 96;
    int cnt = tid;

#pragma unroll 1
    for (int it = 0; it < 13; it++) {
        if (cnt >= NUNIT) break;
        const int x0 = 2 * m;
        const int rc = max(r0 - 1 + rl, 0);

        // feat loads: 8 independent LDG.64, lanes = the two pixels (as-is!)
        const float* fp = fb + rc * WW + x0;
        float2 f[8];
#pragma unroll
        for (int k = 0; k < 8; k++)
            f[k] = *reinterpret_cast<const float2*>(fp + k * HWSZ);

        const float ryv = (ly - (float)(rc * 8 + 4)) * inv;
        const float2 ryd = f2(ryv, ryv);
        const float rxv = (lx - (float)(x0 * 8 + 4)) * inv;
        const float2 rxp = f2(rxv, rxv - s8);

        // ---- layer 0: 10 -> 8, relu. c-outer, one accumulator live ----
        float2 h[8];
#pragma unroll
        for (int c = 0; c < 8; c++) {
            const float4* wc = reinterpret_cast<const float4*>(sw0[c]);
            const float2 bd  = *reinterpret_cast<const float2*>(&sw0[c][20]);
            const float4 w01 = wc[0];
            float2 a = ffma2(f2(w01.x, w01.y), rxp, bd);
            a = ffma2(f2(w01.z, w01.w), ryd, a);
#pragma unroll
            for (int kk = 0; kk < 4; kk++) {     // feats k = 2kk, 2kk+1
                const float4 wp = wc[1 + kk];
                a = ffma2(f2(wp.x, wp.y), f[2*kk],   a);
                a = ffma2(f2(wp.z, wp.w), f[2*kk+1], a);
            }
            h[c] = relu2(a);
        }

        // ---- layer 1: 8 -> 8, relu ----
        float2 g[8];
#pragma unroll
        for (int c = 0; c < 8; c++) {
            const float4* wc = reinterpret_cast<const float4*>(sw1[c]);
            const float2 bd = *reinterpret_cast<const float2*>(&sw1[c][16]);
            float2 a = bd;
#pragma unroll
            for (int kk = 0; kk < 4; kk++) {
                const float4 wp = wc[kk];
                a = ffma2(f2(wp.x, wp.y), h[2*kk],   a);
                a = ffma2(f2(wp.z, wp.w), h[2*kk+1], a);
            }
            g[c] = relu2(a);
        }

        // ---- layer 2: 8 -> 1 ----
        {
            const float4* wc = reinterpret_cast<const float4*>(sw2);
            const float2 bd = *reinterpret_cast<const float2*>(&sw2[16]);
            float2 o = bd;
#pragma unroll
            for (int kk = 0; kk < 4; kk++) {
                const float4 wp = wc[kk];
                o = ffma2(f2(wp.x, wp.y), g[2*kk],   o);
                o = ffma2(f2(wp.z, wp.w), g[2*kk+1], o);
            }
            *reinterpret_cast<float2*>(&sL[rl][x0]) = o;
        }

        // advance unit index by 128 = 1 row + 32 pairs
        rl += 1; m += 32;
        if (m >= 96) { m -= 96; rl += 1; }
        cnt += 128;
    }
    __syncthreads();

    // ---- phase 2: aligned_bilinear x2 from smem tile, float4 stores ----
    // out[o] = interp[max(o-1,0)]; interp[j] even -> t[j/2],
    //                               odd  -> 0.5*(t[j>>1] + t[(j>>1)+1])
    float* ob = out + (size_t)n * (OHH * OWW) + (size_t)(2 * r0) * OWW;
    // 32 output rows x 96 col-groups; stride 128 = 1 row + 32 groups
    int oyl = (tid >= 96) ? 1 : 0;
    int gm  = tid - oyl * 96;
#pragma unroll 1
    for (int it = 0; it < 24; it++) {
        const int oy = 2 * r0 + oyl;
        const int iy = max(oy - 1, 0);
        const int ra = (iy >> 1) - r0 + 1;   // smem slot of row (iy>>1)

        const int cA = max(2 * gm - 1, 0);
        const int cB = 2 * gm;
        const int cC = 2 * gm + 1;

        float va, vb, vc;
        if (iy & 1) {
            va = 0.5f * (sL[ra][cA] + sL[ra + 1][cA]);
            vb = 0.5f * (sL[ra][cB] + sL[ra + 1][cB]);
            vc = 0.5f * (sL[ra][cC] + sL[ra + 1][cC]);
        } else {
            va = sL[ra][cA];
            vb = sL[ra][cB];
            vc = sL[ra][cC];
        }
        float4 o;
        o.x = 0.5f * (va + vb);   // even ox (left-edge clamp folds in at gm==0)
        o.y = vb;                 // odd ox
        o.z = 0.5f * (vb + vc);
        o.w = vc;
        *reinterpret_cast<float4*>(ob + oyl * OWW + 4 * gm) = o;

        oyl += 1; gm += 32;
        if (gm >= 96) { gm -= 96; oyl += 1; }
    }
}

extern "C" void kernel_launch(void* const* d_in, const int* in_sizes, int n_in,
                              void* d_out, int out_size) {
    const float* mask_feats = (const float*)d_in[0];
    const float* params     = (const float*)d_in[1];
    const float* locs       = (const float*)d_in[2];
    const float* soi        = (const float*)d_in[3];
    const int*   im_inds    = (const int*)d_in[4];
    const int*   fpn_levels = (const int*)d_in[5];
    float*       out        = (float*)d_out;

    const int n_inst = in_sizes[4];          // 256
    dim3 grid(HH / TH, n_inst);
    dyn_mask_head_kernel<<<grid, 128>>>(mask_feats, params, locs, soi,
                                        im_inds, fpn_levels, out);
}

// round 10
// speedup vs baseline: 2.3230x; 2.3230x over previous
#include <cuda_runtime.h>

// DynamicMaskHead fused kernel, round 10:
//  = round-3's EXACT hot-loop structure (the only verified no-spill point:
//    4 px/thread, 8x LDG.128 at loop top, c-outer layers with one f32x2
//    accumulator live, duplicated weights in smem, cap (128,4))
//  + only the two changes R4 proved safe in isolation:
//    (a) dead staging pass / dead smem arrays removed
//    (b) hot-loop index math strength-reduced (no integer division)
//  NOTE: layer 0 stays c-outer (R8's kk-outer at the same cap spilled).

#define WW    192
#define HH    128
#define HWSZ  (192*128)
#define CIN   8
#define TH    16
#define NROWS (TH + 1)           // +1 halo row above
#define UPR   (WW/4)             // 48 four-pixel units per row
#define NUNIT (NROWS * UPR)      // 816
#define OWW   384
#define OHH   256
#define NP    169

__device__ __forceinline__ float2 ffma2(float2 a, float2 b, float2 c) {
    float2 d;
    asm("fma.rn.f32x2 %0, %1, %2, %3;"
        : "=l"(reinterpret_cast<unsigned long long&>(d))
        : "l"(reinterpret_cast<unsigned long long&>(a)),
          "l"(reinterpret_cast<unsigned long long&>(b)),
          "l"(reinterpret_cast<unsigned long long&>(c)));
    return d;
}
__device__ __forceinline__ float2 relu2(float2 v) {
    return make_float2(fmaxf(v.x, 0.f), fmaxf(v.y, 0.f));
}
__device__ __forceinline__ float2 f2(float a, float b) { return make_float2(a, b); }

__global__ __launch_bounds__(128, 4) void dyn_mask_head_kernel(
    const float* __restrict__ mask_feats,   // [2, 8, 128, 192]
    const float* __restrict__ params,       // [n_inst, 169]
    const float* __restrict__ locs,         // [n_inst, 2] (x, y)
    const float* __restrict__ soi,          // [5]
    const int*   __restrict__ im_inds,      // [n_inst]
    const int*   __restrict__ fpn_levels,   // [n_inst]
    float*       __restrict__ out)          // [n_inst, 1, 256, 384]
{
    const int n   = blockIdx.y;
    const int r0  = blockIdx.x * TH;
    const int tid = threadIdx.x;

    __shared__ __align__(16) float sw0[8][24]; // w0..w9 dup(20) + bias dup(2) + pad
    __shared__ __align__(16) float sw1[8][20]; // w0..w7 dup(16) + bias dup(2) + pad
    __shared__ __align__(16) float sw2[20];    // w dup(16) + bias dup(2) + pad
    __shared__ __align__(16) float sL[NROWS][WW];

    {
        const float* p = params + n * NP;
        for (int t = tid; t < NP; t += 128) {
            float v = __ldg(p + t);
            if (t < 80) {
                int c = t / 10, j = t - 10 * c;
                sw0[c][2*j] = v; sw0[c][2*j+1] = v;
            } else if (t < 144) {
                int q = t - 80; int c = q >> 3, j = q & 7;
                sw1[c][2*j] = v; sw1[c][2*j+1] = v;
            } else if (t < 152) {
                int j = t - 144;
                sw2[2*j] = v; sw2[2*j+1] = v;
            } else if (t < 160) {
                int c = t - 152;
                sw0[c][20] = v; sw0[c][21] = v;
            } else if (t < 168) {
                int c = t - 160;
                sw1[c][16] = v; sw1[c][17] = v;
            } else {
                sw2[16] = v; sw2[17] = v;
            }
        }
    }
    __syncthreads();

    const int   im  = im_inds[n];
    const float inv = 1.0f / soi[fpn_levels[n]];
    const float lx  = locs[2*n + 0];
    const float ly  = locs[2*n + 1];
    const float* fb = mask_feats + (size_t)im * (CIN * HWSZ);
    const float s8  = 8.0f * inv;

    // ---- phase 1: logits, 4 consecutive pixels per thread per iter ----
    // unit index i = rl*48 + m; per-iter stride 128 = 2 rows + 32 cols
    int rl = (tid >= 96) ? 2 : (tid >= 48 ? 1 : 0);
    int m  = tid - rl * 48;
    int cnt = tid;

#pragma unroll 1
    for (int it = 0; it < 7; it++) {
        if (cnt >= NUNIT) break;
        const int x0 = 4 * m;
        const int rc = max(r0 - 1 + rl, 0);

        // feat loads for this unit (8 independent LDG.128), exactly as R3
        const float* fp = fb + rc * WW + x0;
        float4 f[8];
#pragma unroll
        for (int k = 0; k < 8; k++)
            f[k] = *reinterpret_cast<const float4*>(fp + k * HWSZ);

        const float ryv = (ly - (float)(rc * 8 + 4)) * inv;
        const float2 ryd = f2(ryv, ryv);
        const float rxv = (lx - (float)(x0 * 8 + 4)) * inv;
        const float2 rxA = f2(rxv, rxv - s8);
        const float2 rxB = f2(rxv - 2.f * s8, rxv - 3.f * s8);

        // ---- layer 0: 10 -> 8, relu. c-outer (one acc pair live) ----
        float2 hA[8], hB[8];
#pragma unroll
        for (int c = 0; c < 8; c++) {
            const float4* wc = reinterpret_cast<const float4*>(sw0[c]);
            const float2 bd = *reinterpret_cast<const float2*>(&sw0[c][20]);
            const float4 w01 = wc[0];
            float2 aA = ffma2(f2(w01.x, w01.y), rxA, bd);
            float2 aB = ffma2(f2(w01.x, w01.y), rxB, bd);
            aA = ffma2(f2(w01.z, w01.w), ryd, aA);
            aB = ffma2(f2(w01.z, w01.w), ryd, aB);
#pragma unroll
            for (int kk = 0; kk < 4; kk++) {     // feats k = 2kk, 2kk+1
                const float4 wp = wc[1 + kk];
                aA = ffma2(f2(wp.x, wp.y), f2(f[2*kk].x,   f[2*kk].y),   aA);
                aB = ffma2(f2(wp.x, wp.y), f2(f[2*kk].z,   f[2*kk].w),   aB);
                aA = ffma2(f2(wp.z, wp.w), f2(f[2*kk+1].x, f[2*kk+1].y), aA);
                aB = ffma2(f2(wp.z, wp.w), f2(f[2*kk+1].z, f[2*kk+1].w), aB);
            }
            hA[c] = relu2(aA);
            hB[c] = relu2(aB);
        }

        // ---- layer 1: 8 -> 8, relu ----
        float2 gA[8], gB[8];
#pragma unroll
        for (int c = 0; c < 8; c++) {
            const float4* wc = reinterpret_cast<const float4*>(sw1[c]);
            const float2 bd = *reinterpret_cast<const float2*>(&sw1[c][16]);
            float2 tA = bd, tB = bd;
#pragma unroll
            for (int kk = 0; kk < 4; kk++) {
                const float4 wp = wc[kk];
                tA = ffma2(f2(wp.x, wp.y), hA[2*kk],   tA);
                tB = ffma2(f2(wp.x, wp.y), hB[2*kk],   tB);
                tA = ffma2(f2(wp.z, wp.w), hA[2*kk+1], tA);
                tB = ffma2(f2(wp.z, wp.w), hB[2*kk+1], tB);
            }
            gA[c] = relu2(tA);
            gB[c] = relu2(tB);
        }

        // ---- layer 2: 8 -> 1 ----
        {
            const float4* wc = reinterpret_cast<const float4*>(sw2);
            const float2 bd = *reinterpret_cast<const float2*>(&sw2[16]);
            float2 oA = bd, oB = bd;
#pragma unroll
            for (int kk = 0; kk < 4; kk++) {
                const float4 wp = wc[kk];
                oA = ffma2(f2(wp.x, wp.y), gA[2*kk],   oA);
                oB = ffma2(f2(wp.x, wp.y), gB[2*kk],   oB);
                oA = ffma2(f2(wp.z, wp.w), gA[2*kk+1], oA);
                oB = ffma2(f2(wp.z, wp.w), gB[2*kk+1], oB);
            }
            *reinterpret_cast<float4*>(&sL[rl][x0]) =
                make_float4(oA.x, oA.y, oB.x, oB.y);
        }

        // advance unit index by 128 = 2 rows + 32 cols (division-free)
        rl += 2; m += 32;
        if (m >= 48) { m -= 48; rl += 1; }
        cnt += 128;
    }
    __syncthreads();

    // ---- phase 2: aligned_bilinear x2 from smem tile, float4 stores ----
    // out[o] = interp[max(o-1,0)]; interp[j] even -> t[j/2],
    //                               odd  -> 0.5*(t[j>>1] + t[(j>>1)+1])
    float* ob = out + (size_t)n * (OHH * OWW) + (size_t)(2 * r0) * OWW;
    // 32 output rows x 96 col-groups; stride 128 = 1 row + 32 groups
    int oyl = (tid >= 96) ? 1 : 0;
    int gm  = tid - oyl * 96;
#pragma unroll 1
    for (int it = 0; it < 24; it++) {
        const int oy = 2 * r0 + oyl;
        const int iy = max(oy - 1, 0);
        const int ra = (iy >> 1) - r0 + 1;   // smem slot of row (iy>>1)

        const int cA = max(2 * gm - 1, 0);
        const int cB = 2 * gm;
        const int cC = 2 * gm + 1;

        float va, vb, vc;
        if (iy & 1) {
            va = 0.5f * (sL[ra][cA] + sL[ra + 1][cA]);
            vb = 0.5f * (sL[ra][cB] + sL[ra + 1][cB]);
            vc = 0.5f * (sL[ra][cC] + sL[ra + 1][cC]);
        } else {
            va = sL[ra][cA];
            vb = sL[ra][cB];
            vc = sL[ra][cC];
        }
        float4 o;
        o.x = 0.5f * (va + vb);   // even ox (left-edge clamp folds in at gm==0)
        o.y = vb;                 // odd ox
        o.z = 0.5f * (vb + vc);
        o.w = vc;
        *reinterpret_cast<float4*>(ob + oyl * OWW + 4 * gm) = o;

        oyl += 1; gm += 32;
        if (gm >= 96) { gm -= 96; oyl += 1; }
    }
}

extern "C" void kernel_launch(void* const* d_in, const int* in_sizes, int n_in,
                              void* d_out, int out_size) {
    const float* mask_feats = (const float*)d_in[0];
    const float* params     = (const float*)d_in[1];
    const float* locs       = (const float*)d_in[2];
    const float* soi        = (const float*)d_in[3];
    const int*   im_inds    = (const int*)d_in[4];
    const int*   fpn_levels = (const int*)d_in[5];
    float*       out        = (float*)d_out;

    const int n_inst = in_sizes[4];          // 256
    dim3 grid(HH / TH, n_inst);
    dyn_mask_head_kernel<<<grid, 128>>>(mask_feats, params, locs, soi,
                                        im_inds, fpn_levels, out);
}

// round 11
// speedup vs baseline: 6.5705x; 2.8284x over previous
#include <cuda_runtime.h>

// DynamicMaskHead fused kernel, round 11:
//  = round-3 VERBATIM hot-loop form — the only allocation-clean point found:
//    * phase-1 indices derived per-iteration by DIVISION from i = tid+it*128
//      (no loop-carried counters: R8/R10 proved carried rl/m/cnt + carry
//      branch trip ptxas into spilling this body)
//    * c-outer layers, one f32x2 accumulator pair live
//    * 8x LDG.128 feats at loop top, duplicated weights in smem (LDS.128 =
//      two ready [w,w] splats, warp-uniform broadcast)
//    * __launch_bounds__(128,4)
//  Only change vs R3: the dead first staging pass + dead smem arrays removed
//  (outside the hot loop; registers dead before the loop begins).

#define WW    192
#define HH    128
#define HWSZ  (192*128)
#define CIN   8
#define TH    16
#define NROWS (TH + 1)           // +1 halo row above
#define UPR   (WW/4)             // 48 four-pixel units per row
#define NUNIT (NROWS * UPR)      // 816
#define OWW   384
#define OHH   256
#define NP    169

__device__ __forceinline__ float2 ffma2(float2 a, float2 b, float2 c) {
    float2 d;
    asm("fma.rn.f32x2 %0, %1, %2, %3;"
        : "=l"(reinterpret_cast<unsigned long long&>(d))
        : "l"(reinterpret_cast<unsigned long long&>(a)),
          "l"(reinterpret_cast<unsigned long long&>(b)),
          "l"(reinterpret_cast<unsigned long long&>(c)));
    return d;
}
__device__ __forceinline__ float2 relu2(float2 v) {
    return make_float2(fmaxf(v.x, 0.f), fmaxf(v.y, 0.f));
}
__device__ __forceinline__ float2 f2(float a, float b) { return make_float2(a, b); }

__global__ __launch_bounds__(128, 4) void dyn_mask_head_kernel(
    const float* __restrict__ mask_feats,   // [2, 8, 128, 192]
    const float* __restrict__ params,       // [n_inst, 169]
    const float* __restrict__ locs,         // [n_inst, 2] (x, y)
    const float* __restrict__ soi,          // [5]
    const int*   __restrict__ im_inds,      // [n_inst]
    const int*   __restrict__ fpn_levels,   // [n_inst]
    float*       __restrict__ out)          // [n_inst, 1, 256, 384]
{
    const int n   = blockIdx.y;
    const int r0  = blockIdx.x * TH;
    const int tid = threadIdx.x;

    __shared__ __align__(16) float sw1[8][20]; // w0..w7 dup(16) + bias dup(2) + pad
    __shared__ __align__(16) float sw2[20];    // w dup(16) + bias dup(2) + pad
    __shared__ __align__(16) float sL[NROWS][WW];
    __shared__ __align__(16) float sw0[8][24]; // w0..w9 dup(20) + bias dup(2) + pad

    {
        const float* p = params + n * NP;
        for (int t = tid; t < NP; t += 128) {
            float v = __ldg(p + t);
            if (t < 80) {
                int c = t / 10, j = t - 10 * c;
                sw0[c][2*j] = v; sw0[c][2*j+1] = v;
            } else if (t < 144) {
                int q = t - 80; int c = q >> 3, j = q & 7;
                sw1[c][2*j] = v; sw1[c][2*j+1] = v;
            } else if (t < 152) {
                int j = t - 144;
                sw2[2*j] = v; sw2[2*j+1] = v;
            } else if (t < 160) {
                int c = t - 152;
                sw0[c][20] = v; sw0[c][21] = v;
            } else if (t < 168) {
                int c = t - 160;
                sw1[c][16] = v; sw1[c][17] = v;
            } else {
                sw2[16] = v; sw2[17] = v;
            }
        }
    }
    __syncthreads();

    const int   im  = im_inds[n];
    const float inv = 1.0f / soi[fpn_levels[n]];
    const float lx  = locs[2*n + 0];
    const float ly  = locs[2*n + 1];
    const float* fb = mask_feats + (size_t)im * (CIN * HWSZ);
    const float s8  = 8.0f * inv;

    // ---- phase 1: logits, 4 consecutive pixels per thread per iter ----
    // R3-form indexing: i derived fresh each iteration, rl/m by division
    // (dead after address computation -> allocation-clean).
#pragma unroll 1
    for (int it = 0; it < 7; it++) {
        const int i = tid + it * 128;
        if (i >= NUNIT) break;
        const int rl = i / UPR;
        const int m  = i - rl * UPR;
        const int x0 = 4 * m;
        const int rc = max(r0 - 1 + rl, 0);

        const float* fp = fb + rc * WW + x0;
        float4 f[8];
#pragma unroll
        for (int k = 0; k < 8; k++)
            f[k] = *reinterpret_cast<const float4*>(fp + k * HWSZ);

        const float ryv = (ly - (float)(rc * 8 + 4)) * inv;
        const float2 ryd = f2(ryv, ryv);
        const float rxv = (lx - (float)(x0 * 8 + 4)) * inv;
        const float2 rxA = f2(rxv, rxv - s8);
        const float2 rxB = f2(rxv - 2.f * s8, rxv - 3.f * s8);

        // ---- layer 0: 10 -> 8, relu. c-outer (one acc pair live) ----
        float2 hA[8], hB[8];
#pragma unroll
        for (int c = 0; c < 8; c++) {
            const float4* wc = reinterpret_cast<const float4*>(sw0[c]);
            const float2 bd = *reinterpret_cast<const float2*>(&sw0[c][20]);
            float4 w01 = wc[0];
            float2 aA = ffma2(f2(w01.x, w01.y), rxA, bd);
            float2 aB = ffma2(f2(w01.x, w01.y), rxB, bd);
            aA = ffma2(f2(w01.z, w01.w), ryd, aA);
            aB = ffma2(f2(w01.z, w01.w), ryd, aB);
#pragma unroll
            for (int kk = 0; kk < 4; kk++) {     // feats k = 2kk, 2kk+1
                float4 wp = wc[1 + kk];
                aA = ffma2(f2(wp.x, wp.y), f2(f[2*kk].x,   f[2*kk].y),   aA);
                aB = ffma2(f2(wp.x, wp.y), f2(f[2*kk].z,   f[2*kk].w),   aB);
                aA = ffma2(f2(wp.z, wp.w), f2(f[2*kk+1].x, f[2*kk+1].y), aA);
                aB = ffma2(f2(wp.z, wp.w), f2(f[2*kk+1].z, f[2*kk+1].w), aB);
            }
            hA[c] = relu2(aA);
            hB[c] = relu2(aB);
        }

        // ---- layer 1: 8 -> 8, relu ----
        float2 gA[8], gB[8];
#pragma unroll
        for (int c = 0; c < 8; c++) {
            const float4* wc = reinterpret_cast<const float4*>(sw1[c]);
            const float2 bd = *reinterpret_cast<const float2*>(&sw1[c][16]);
            float2 aA = bd, aB = bd;
#pragma unroll
            for (int kk = 0; kk < 4; kk++) {
                float4 wp = wc[kk];
                aA = ffma2(f2(wp.x, wp.y), hA[2*kk],   aA);
                aB = ffma2(f2(wp.x, wp.y), hB[2*kk],   aB);
                aA = ffma2(f2(wp.z, wp.w), hA[2*kk+1], aA);
                aB = ffma2(f2(wp.z, wp.w), hB[2*kk+1], aB);
            }
            gA[c] = relu2(aA);
            gB[c] = relu2(aB);
        }

        // ---- layer 2: 8 -> 1 ----
        {
            const float4* wc = reinterpret_cast<const float4*>(sw2);
            const float2 bd = *reinterpret_cast<const float2*>(&sw2[16]);
            float2 oA = bd, oB = bd;
#pragma unroll
            for (int kk = 0; kk < 4; kk++) {
                float4 wp = wc[kk];
                oA = ffma2(f2(wp.x, wp.y), gA[2*kk],   oA);
                oB = ffma2(f2(wp.x, wp.y), gB[2*kk],   oB);
                oA = ffma2(f2(wp.z, wp.w), gA[2*kk+1], oA);
                oB = ffma2(f2(wp.z, wp.w), gB[2*kk+1], oB);
            }
            float4 v = make_float4(oA.x, oA.y, oB.x, oB.y);
            *reinterpret_cast<float4*>(&sL[rl][x0]) = v;
        }
    }
    __syncthreads();

    // ---- phase 2: aligned_bilinear x2 from smem tile, float4 stores ----
    // out[o] = interp[max(o-1,0)]; interp[j] even -> t[j/2],
    //                               odd  -> 0.5*(t[j>>1] + t[(j>>1)+1])
    float* ob = out + (size_t)n * (OHH * OWW) + (size_t)(2 * r0) * OWW;
    const int NG = 32 * (WW / 2);  // 32 output rows x 96 groups of 4 cols
    for (int g = tid; g < NG; g += 128) {
        const int oyl = g / 96;
        const int m   = g - oyl * 96;
        const int oy  = 2 * r0 + oyl;
        const int iy  = max(oy - 1, 0);
        const int ra  = (iy >> 1) - r0 + 1;   // smem slot of row (iy>>1)

        const int cA = max(2 * m - 1, 0);
        const int cB = 2 * m;
        const int cC = 2 * m + 1;

        float va, vb, vc;
        if (iy & 1) {
            va = 0.5f * (sL[ra][cA] + sL[ra + 1][cA]);
            vb = 0.5f * (sL[ra][cB] + sL[ra + 1][cB]);
            vc = 0.5f * (sL[ra][cC] + sL[ra + 1][cC]);
        } else {
            va = sL[ra][cA];
            vb = sL[ra][cB];
            vc = sL[ra][cC];
        }
        float4 o;
        o.x = 0.5f * (va + vb);   // even ox (left-edge clamp folds in at m==0)
        o.y = vb;                 // odd ox
        o.z = 0.5f * (vb + vc);
        o.w = vc;
        *reinterpret_cast<float4*>(ob + oyl * OWW + 4 * m) = o;
    }
}

extern "C" void kernel_launch(void* const* d_in, const int* in_sizes, int n_in,
                              void* d_out, int out_size) {
    const float* mask_feats = (const float*)d_in[0];
    const float* params     = (const float*)d_in[1];
    const float* locs       = (const float*)d_in[2];
    const float* soi        = (const float*)d_in[3];
    const int*   im_inds    = (const int*)d_in[4];
    const int*   fpn_levels = (const int*)d_in[5];
    float*       out        = (float*)d_out;

    const int n_inst = in_sizes[4];          // 256
    dim3 grid(HH / TH, n_inst);
    dyn_mask_head_kernel<<<grid, 128>>>(mask_feats, params, locs, soi,
                                        im_inds, fpn_levels, out);
}